// round 5
// baseline (speedup 1.0000x reference)
#include <cuda_runtime.h>

// Problem constants
#define BC_C   9
#define BC_FR  64
#define BC_T   64
#define BC_P   4
#define BC_E   192
#define BC_NF  16
#define BC_NT  16

#define W_ROW_PAD 36   // 32 floats of W per e-pair + 4 pad -> conflict-free LDS.128

using u64 = unsigned long long;

__device__ __forceinline__ u64 pack2(float lo, float hi) {
    u64 r;
    asm("mov.b64 %0, {%1, %2};" : "=l"(r) : "f"(lo), "f"(hi));
    return r;
}
__device__ __forceinline__ void unpack2(u64 v, float& lo, float& hi) {
    asm("mov.b64 {%0, %1}, %2;" : "=f"(lo), "=f"(hi) : "l"(v));
}
// d = a * b + d  on packed f32x2 (Blackwell FFMA2 — only reachable via PTX)
__device__ __forceinline__ void fma2(u64& d, u64 a, u64 b) {
    asm("fma.rn.f32x2 %0, %1, %2, %0;" : "+l"(d) : "l"(a), "l"(b));
}

// Grid: (C=9, B). Block: 192 threads, 3 blocks/SM (e-pair split cuts regs to
// fit 18 warps — round-3 kernel was latency-bound at 12 warps / occ 17%).
//   q = tid % 96 -> e-pair (e = 2q, 2q+1); W for these 2 e rows in 16 u64 regs
//   g = tid / 96 -> f-half: f = 8g .. 8g+7, all 16 t each
__global__ __launch_bounds__(192, 3)
void patch_embed_kernel(const float* __restrict__ x,
                        const float* __restrict__ W,
                        const float* __restrict__ bvec,
                        const float* __restrict__ chEmb,
                        const float* __restrict__ spEmb,
                        const float* __restrict__ timePos,
                        const float* __restrict__ freqPos,
                        const int*   __restrict__ spIdx,
                        float* __restrict__ out)
{
    const int c   = blockIdx.x;   // 0..8
    const int b   = blockIdx.y;   // 0..B-1
    const int tid = threadIdx.x;  // 0..191
    const int q   = tid % 96;
    const int g   = tid / 96;     // 0..1
    const int e0  = q * 2;

    __shared__ __align__(16) float xs[BC_FR * BC_T];          // 16 KB input plane
    __shared__ __align__(16) float ws[96 * W_ROW_PAD];        // 13.5 KB padded W

    // Stage x plane (coalesced float4).
    {
        const float4* gx = reinterpret_cast<const float4*>(
            x + (size_t)(b * BC_C + c) * (BC_FR * BC_T));
        float4* sx = reinterpret_cast<float4*>(xs);
        #pragma unroll
        for (int i = tid; i < (BC_FR * BC_T) / 4; i += 192)
            sx[i] = gx[i];
    }

    // Stage W (3072 floats) coalesced into padded smem.
    // Global float4 j: e = j>>2, part = j&3. Dest row r = e>>1 (e-pair),
    // half = e&1: ws[r*36 + half*16 + part*4].
    {
        const float4* gw = reinterpret_cast<const float4*>(W);
        #pragma unroll
        for (int j = tid; j < (BC_E * 16) / 4; j += 192) {
            int e    = j >> 2;
            int part = j & 3;
            *reinterpret_cast<float4*>(
                &ws[(e >> 1) * W_ROW_PAD + (e & 1) * 16 + part * 4]) = gw[j];
        }
    }

    // Per-e static bias: b + channel + spatial[spatial_idx[c]]  (float2 per e-pair)
    const int sidx = __ldg(spIdx + c);
    float2 bb = *reinterpret_cast<const float2*>(bvec + e0);
    float2 ce = *reinterpret_cast<const float2*>(chEmb + c * BC_E + e0);
    float2 se = *reinterpret_cast<const float2*>(spEmb + sidx * BC_E + e0);
    float2 bs;
    bs.x = bb.x + ce.x + se.x;
    bs.y = bb.y + ce.y + se.y;

    // Per-f base = static + freq_pos[f], for this thread's 8 f values.
    float2 base[8];
    #pragma unroll
    for (int fi = 0; fi < 8; fi++) {
        const int f = g * 8 + fi;
        float2 fe = *reinterpret_cast<const float2*>(freqPos + f * BC_E + e0);
        base[fi].x = bs.x + fe.x;
        base[fi].y = bs.y + fe.y;
    }

    __syncthreads();

    // Pull W for this thread's 2 e rows into registers from padded smem.
    // Lane addresses q*36 floats apart -> per 8-lane phase banks 4q mod 32
    // all distinct -> conflict-free LDS.128.
    u64 w[16];
    #pragma unroll
    for (int i = 0; i < 4; i++) {
        float4 v0 = *reinterpret_cast<const float4*>(&ws[q * W_ROW_PAD + i * 4]);
        float4 v1 = *reinterpret_cast<const float4*>(&ws[q * W_ROW_PAD + 16 + i * 4]);
        w[2 * i]         = pack2(v0.x, v0.y);
        w[2 * i + 1]     = pack2(v0.z, v0.w);
        w[8 + 2 * i]     = pack2(v1.x, v1.y);
        w[8 + 2 * i + 1] = pack2(v1.z, v1.w);
    }

    float* outp = out + ((size_t)b * (BC_C * BC_NF * BC_NT)
                         + c * (BC_NF * BC_NT)) * BC_E;

    // t unrolled by 2: 4 independent FMA2 chains per fi iteration.
    #pragma unroll 1
    for (int t = 0; t < BC_NT; t += 2) {
        float2 tp0 = *reinterpret_cast<const float2*>(timePos + t * BC_E + e0);
        float2 tp1 = *reinterpret_cast<const float2*>(timePos + (t + 1) * BC_E + e0);

        #pragma unroll
        for (int fi = 0; fi < 8; fi++) {
            const int f = g * 8 + fi;

            // Patch x for t and t+1: broadcast LDS (all lanes share (f,t)).
            u64 xp0[8], xp1[8];
            #pragma unroll
            for (int u = 0; u < 4; u++) {
                const float* rowp = &xs[(f * 4 + u) * BC_T];
                ulonglong2 v0 = *reinterpret_cast<const ulonglong2*>(rowp + t * 4);
                ulonglong2 v1 = *reinterpret_cast<const ulonglong2*>(rowp + (t + 1) * 4);
                xp0[2 * u] = v0.x;  xp0[2 * u + 1] = v0.y;
                xp1[2 * u] = v1.x;  xp1[2 * u + 1] = v1.y;
            }

            u64 a0 = pack2(base[fi].x + tp0.x, 0.0f);
            u64 a1 = pack2(base[fi].y + tp0.y, 0.0f);
            u64 b0 = pack2(base[fi].x + tp1.x, 0.0f);
            u64 b1 = pack2(base[fi].y + tp1.y, 0.0f);

            #pragma unroll
            for (int k = 0; k < 8; k++) {
                fma2(a0, xp0[k], w[k]);
                fma2(a1, xp0[k], w[8 + k]);
                fma2(b0, xp1[k], w[k]);
                fma2(b1, xp1[k], w[8 + k]);
            }

            float2 r0, r1;
            { float lo, hi; unpack2(a0, lo, hi); r0.x = lo + hi; }
            { float lo, hi; unpack2(a1, lo, hi); r0.y = lo + hi; }
            { float lo, hi; unpack2(b0, lo, hi); r1.x = lo + hi; }
            { float lo, hi; unpack2(b1, lo, hi); r1.y = lo + hi; }

            float* op = outp + (size_t)(f * BC_NT + t) * BC_E + e0;
            *reinterpret_cast<float2*>(op)        = r0;
            *reinterpret_cast<float2*>(op + BC_E) = r1;
        }
    }
}

extern "C" void kernel_launch(void* const* d_in, const int* in_sizes, int n_in,
                              void* d_out, int out_size)
{
    const float* x    = (const float*)d_in[0];
    const float* W    = (const float*)d_in[1];
    const float* bv   = (const float*)d_in[2];
    const float* ch   = (const float*)d_in[3];
    const float* sp   = (const float*)d_in[4];
    const float* tpos = (const float*)d_in[5];
    const float* fpos = (const float*)d_in[6];
    const int*   sidx = (const int*)d_in[7];
    float* out = (float*)d_out;

    const int Bx = in_sizes[0] / (BC_C * BC_FR * BC_T);

    dim3 grid(BC_C, Bx);
    patch_embed_kernel<<<grid, 192>>>(x, W, bv, ch, sp, tpos, fpos, sidx, out);
}

// round 6
// speedup vs baseline: 1.1127x; 1.1127x over previous
#include <cuda_runtime.h>

// Problem constants
#define BC_C   9
#define BC_FR  64
#define BC_T   64
#define BC_P   4
#define BC_E   192
#define BC_NF  16
#define BC_NT  16

#define W_ROW_PAD 68   // 64 floats of W per e-quad + 4 pad -> conflict-free LDS.128

using u64 = unsigned long long;

__device__ __forceinline__ u64 pack2(float lo, float hi) {
    u64 r;
    asm("mov.b64 %0, {%1, %2};" : "=l"(r) : "f"(lo), "f"(hi));
    return r;
}
__device__ __forceinline__ void unpack2(u64 v, float& lo, float& hi) {
    asm("mov.b64 {%0, %1}, %2;" : "=f"(lo), "=f"(hi) : "l"(v));
}
// d = a * b + d  on packed f32x2 (Blackwell FFMA2 — only reachable via PTX)
__device__ __forceinline__ void fma2(u64& d, u64 a, u64 b) {
    asm("fma.rn.f32x2 %0, %1, %2, %0;" : "+l"(d) : "l"(a), "l"(b));
}
// Streaming (evict-first) 16B store: output is write-once, never re-read.
__device__ __forceinline__ void stg_cs(float* p, float4 v) {
    asm volatile("st.global.cs.v4.f32 [%0], {%1, %2, %3, %4};"
                 :: "l"(p), "f"(v.x), "f"(v.y), "f"(v.z), "f"(v.w) : "memory");
}
// cp.async 16B GMEM -> SMEM (LDGSTS)
__device__ __forceinline__ void cp_async16(void* smem_dst, const void* gmem_src) {
    unsigned saddr = (unsigned)__cvta_generic_to_shared(smem_dst);
    asm volatile("cp.async.cg.shared.global [%0], [%1], 16;"
                 :: "r"(saddr), "l"(gmem_src) : "memory");
}

// Grid: (C=9, B). Block: 192 threads. One block = full 64x64 plane of one (b,c).
//   q = tid % 48 -> e-quad (e = 4q..4q+3), W for these 4 e rows held in regs
//   g = tid / 48 -> f-group: f = 4g..4g+3, all 16 t each
// (Round-4 e-pair split regressed: it doubled LDS + halved store width. The
//  4-e layout's 1 LDS.128 + 1 STG.128 per output-quad is the minimum L1 work.)
__global__ __launch_bounds__(192, 2)
void patch_embed_kernel(const float* __restrict__ x,
                        const float* __restrict__ W,
                        const float* __restrict__ bvec,
                        const float* __restrict__ chEmb,
                        const float* __restrict__ spEmb,
                        const float* __restrict__ timePos,
                        const float* __restrict__ freqPos,
                        const int*   __restrict__ spIdx,
                        float* __restrict__ out)
{
    const int c   = blockIdx.x;   // 0..8
    const int b   = blockIdx.y;   // 0..B-1
    const int tid = threadIdx.x;  // 0..191
    const int q   = tid % 48;
    const int g   = tid / 48;     // 0..3
    const int e0  = q * 4;

    __shared__ __align__(16) float xs[BC_FR * BC_T];          // 16 KB input plane
    __shared__ __align__(16) float ws[48 * W_ROW_PAD];        // ~13 KB padded W

    // Stage x plane via cp.async (coalesced 16B, no reg round-trip).
    {
        const float4* gx = reinterpret_cast<const float4*>(
            x + (size_t)(b * BC_C + c) * (BC_FR * BC_T));
        #pragma unroll
        for (int i = tid; i < (BC_FR * BC_T) / 4; i += 192)
            cp_async16(&reinterpret_cast<float4*>(xs)[i], &gx[i]);
    }
    // Stage W (3072 floats) via cp.async into padded smem: global float4 j ->
    // row r = j/16 (e-quad), col = (j%16)*4 within the 64-float row.
    {
        const float4* gw = reinterpret_cast<const float4*>(W);
        #pragma unroll
        for (int j = tid; j < (BC_E * 16) / 4; j += 192) {
            int r   = j >> 4;
            int col = (j & 15) << 2;
            cp_async16(&ws[r * W_ROW_PAD + col], &gw[j]);
        }
    }
    asm volatile("cp.async.commit_group;" ::: "memory");

    // Per-e static bias: b + channel + spatial[spatial_idx[c]] (overlaps cp.async)
    const int sidx = __ldg(spIdx + c);
    float4 bb = *reinterpret_cast<const float4*>(bvec + e0);
    float4 ce = *reinterpret_cast<const float4*>(chEmb + c * BC_E + e0);
    float4 se = *reinterpret_cast<const float4*>(spEmb + sidx * BC_E + e0);
    float4 bs;
    bs.x = bb.x + ce.x + se.x;
    bs.y = bb.y + ce.y + se.y;
    bs.z = bb.z + ce.z + se.z;
    bs.w = bb.w + ce.w + se.w;

    // Per-f base = static + freq_pos[f], for this thread's 4 f values.
    float4 base[4];
    #pragma unroll
    for (int fi = 0; fi < 4; fi++) {
        const int f = g * 4 + fi;
        float4 fe = *reinterpret_cast<const float4*>(freqPos + f * BC_E + e0);
        base[fi].x = bs.x + fe.x;
        base[fi].y = bs.y + fe.y;
        base[fi].z = bs.z + fe.z;
        base[fi].w = bs.w + fe.w;
    }

    asm volatile("cp.async.wait_group 0;" ::: "memory");
    __syncthreads();

    // Pull W for this thread's 4 e rows into regs (conflict-free padded LDS.128).
    u64 w[32];
    #pragma unroll
    for (int i = 0; i < 16; i++) {
        float4 v = *reinterpret_cast<const float4*>(&ws[q * W_ROW_PAD + i * 4]);
        w[2 * i]     = pack2(v.x, v.y);
        w[2 * i + 1] = pack2(v.z, v.w);
    }

    float* outp = out + ((size_t)b * (BC_C * BC_NF * BC_NT)
                         + c * (BC_NF * BC_NT)) * BC_E;

    // t unrolled by 2: 8 independent FMA2 chains per fi iteration.
    #pragma unroll 1
    for (int t = 0; t < BC_NT; t += 2) {
        float4 tp0 = *reinterpret_cast<const float4*>(timePos + t * BC_E + e0);
        float4 tp1 = *reinterpret_cast<const float4*>(timePos + (t + 1) * BC_E + e0);

        #pragma unroll
        for (int fi = 0; fi < 4; fi++) {
            const int f = g * 4 + fi;

            // Patch x for t and t+1: broadcast LDS (all lanes share (f,t)).
            u64 xp0[8], xp1[8];
            #pragma unroll
            for (int u = 0; u < 4; u++) {
                const float* rowp = &xs[(f * 4 + u) * BC_T];
                ulonglong2 v0 = *reinterpret_cast<const ulonglong2*>(rowp + t * 4);
                ulonglong2 v1 = *reinterpret_cast<const ulonglong2*>(rowp + (t + 1) * 4);
                xp0[2 * u] = v0.x;  xp0[2 * u + 1] = v0.y;
                xp1[2 * u] = v1.x;  xp1[2 * u + 1] = v1.y;
            }

            // Accumulator init {base, tp}: FMA2 lo/hi halves accumulate
            // independent partial sums, and the final lo+hi folds BOTH biases
            // for free (removes 8 FADD per iteration vs pre-adding).
            u64 a0 = pack2(base[fi].x, tp0.x);
            u64 a1 = pack2(base[fi].y, tp0.y);
            u64 a2 = pack2(base[fi].z, tp0.z);
            u64 a3 = pack2(base[fi].w, tp0.w);
            u64 b0 = pack2(base[fi].x, tp1.x);
            u64 b1 = pack2(base[fi].y, tp1.y);
            u64 b2 = pack2(base[fi].z, tp1.z);
            u64 b3 = pack2(base[fi].w, tp1.w);

            #pragma unroll
            for (int k = 0; k < 8; k++) {
                fma2(a0, xp0[k], w[k]);
                fma2(a1, xp0[k], w[8 + k]);
                fma2(a2, xp0[k], w[16 + k]);
                fma2(a3, xp0[k], w[24 + k]);
                fma2(b0, xp1[k], w[k]);
                fma2(b1, xp1[k], w[8 + k]);
                fma2(b2, xp1[k], w[16 + k]);
                fma2(b3, xp1[k], w[24 + k]);
            }

            float4 r0, r1;
            { float lo, hi; unpack2(a0, lo, hi); r0.x = lo + hi; }
            { float lo, hi; unpack2(a1, lo, hi); r0.y = lo + hi; }
            { float lo, hi; unpack2(a2, lo, hi); r0.z = lo + hi; }
            { float lo, hi; unpack2(a3, lo, hi); r0.w = lo + hi; }
            { float lo, hi; unpack2(b0, lo, hi); r1.x = lo + hi; }
            { float lo, hi; unpack2(b1, lo, hi); r1.y = lo + hi; }
            { float lo, hi; unpack2(b2, lo, hi); r1.z = lo + hi; }
            { float lo, hi; unpack2(b3, lo, hi); r1.w = lo + hi; }

            float* op = outp + (size_t)(f * BC_NT + t) * BC_E + e0;
            stg_cs(op, r0);
            stg_cs(op + BC_E, r1);
        }
    }
}

extern "C" void kernel_launch(void* const* d_in, const int* in_sizes, int n_in,
                              void* d_out, int out_size)
{
    const float* x    = (const float*)d_in[0];
    const float* W    = (const float*)d_in[1];
    const float* bv   = (const float*)d_in[2];
    const float* ch   = (const float*)d_in[3];
    const float* sp   = (const float*)d_in[4];
    const float* tpos = (const float*)d_in[5];
    const float* fpos = (const float*)d_in[6];
    const int*   sidx = (const int*)d_in[7];
    float* out = (float*)d_out;

    const int Bx = in_sizes[0] / (BC_C * BC_FR * BC_T);

    dim3 grid(BC_C, Bx);
    patch_embed_kernel<<<grid, 192>>>(x, W, bv, ch, sp, tpos, fpos, sidx, out);
}